// round 3
// baseline (speedup 1.0000x reference)
#include <cuda_runtime.h>

// CrossNet: y_{k+1} = y_k * (y_k . w_k + 1) + b_k, 3 fused layers.
// B=16384 rows, D=2048 cols, fp32.
// R=4 rows per CTA. w/b reloaded per layer (L1-hit) to cut register
// pressure -> 3 CTAs/SM. One barrier per layer: warp partials go to a
// per-layer smem buffer; every thread broadcast-reads all 16 and sums.

#define D 2048
#define VEC (D / 4)          // 512 float4 per row
#define THREADS 512
#define NWARP (THREADS / 32) // 16
#define R 4                  // rows per CTA

__global__ __launch_bounds__(THREADS, 3)
void crossnet_kernel(const float4* __restrict__ x,
                     const float4* __restrict__ w1, const float4* __restrict__ b1,
                     const float4* __restrict__ w2, const float4* __restrict__ b2,
                     const float4* __restrict__ w3, const float4* __restrict__ b3,
                     float4* __restrict__ out)
{
    // per-layer double-buffered warp partials: [layer][warp] -> 4 rows
    __shared__ float4 sh[3][NWARP];

    const int t    = threadIdx.x;          // column slice 0..511
    const int lane = t & 31;
    const int wid  = t >> 5;
    const long long base = (long long)blockIdx.x * (R * VEC) + t;

    // 4 independent row loads (streaming; row data has no reuse)
    float4 y[R];
    #pragma unroll
    for (int r = 0; r < R; ++r)
        y[r] = __ldcs(&x[base + (long long)r * VEC]);

    #pragma unroll
    for (int layer = 0; layer < 3; ++layer) {
        // reload per-column weight for this layer (L1/L2 hit after wave 1)
        const float4* wp = (layer == 0) ? w1 : (layer == 1) ? w2 : w3;
        const float4 wv = __ldg(&wp[t]);

        // partial dot per row
        float p[R];
        #pragma unroll
        for (int r = 0; r < R; ++r)
            p[r] = y[r].x * wv.x + y[r].y * wv.y + y[r].z * wv.z + y[r].w * wv.w;

        // warp butterfly reduce, all 4 rows together
        #pragma unroll
        for (int off = 16; off > 0; off >>= 1) {
            #pragma unroll
            for (int r = 0; r < R; ++r)
                p[r] += __shfl_xor_sync(0xFFFFFFFFu, p[r], off);
        }

        if (lane == 0) sh[layer][wid] = make_float4(p[0], p[1], p[2], p[3]);
        __syncthreads();

        // every thread sums all 16 warp partials (broadcast LDS, no conflicts)
        float4 acc = sh[layer][0];
        #pragma unroll
        for (int j = 1; j < NWARP; ++j) {
            float4 v = sh[layer][j];
            acc.x += v.x; acc.y += v.y; acc.z += v.z; acc.w += v.w;
        }

        const float4* bp = (layer == 0) ? b1 : (layer == 1) ? b2 : b3;
        const float4 bv = __ldg(&bp[t]);

        // y = y * (s + 1) + b   (== y*s + b + y)
        const float s0 = acc.x + 1.0f;
        const float s1 = acc.y + 1.0f;
        const float s2 = acc.z + 1.0f;
        const float s3 = acc.w + 1.0f;

        y[0].x = fmaf(y[0].x, s0, bv.x); y[0].y = fmaf(y[0].y, s0, bv.y);
        y[0].z = fmaf(y[0].z, s0, bv.z); y[0].w = fmaf(y[0].w, s0, bv.w);
        y[1].x = fmaf(y[1].x, s1, bv.x); y[1].y = fmaf(y[1].y, s1, bv.y);
        y[1].z = fmaf(y[1].z, s1, bv.z); y[1].w = fmaf(y[1].w, s1, bv.w);
        y[2].x = fmaf(y[2].x, s2, bv.x); y[2].y = fmaf(y[2].y, s2, bv.y);
        y[2].z = fmaf(y[2].z, s2, bv.z); y[2].w = fmaf(y[2].w, s2, bv.w);
        y[3].x = fmaf(y[3].x, s3, bv.x); y[3].y = fmaf(y[3].y, s3, bv.y);
        y[3].z = fmaf(y[3].z, s3, bv.z); y[3].w = fmaf(y[3].w, s3, bv.w);
        // next layer writes sh[layer+1] -> no trailing barrier needed
    }

    #pragma unroll
    for (int r = 0; r < R; ++r)
        __stcs(&out[base + (long long)r * VEC], y[r]);
}

extern "C" void kernel_launch(void* const* d_in, const int* in_sizes, int n_in,
                              void* d_out, int out_size)
{
    const float4* x  = (const float4*)d_in[0];
    const float4* w1 = (const float4*)d_in[1];
    const float4* b1 = (const float4*)d_in[2];
    const float4* w2 = (const float4*)d_in[3];
    const float4* b2 = (const float4*)d_in[4];
    const float4* w3 = (const float4*)d_in[5];
    const float4* b3 = (const float4*)d_in[6];
    float4* out = (float4*)d_out;

    const int B = in_sizes[0] / D;   // 16384
    crossnet_kernel<<<B / R, THREADS>>>(x, w1, b1, w2, b2, w3, b3, out);
}

// round 4
// speedup vs baseline: 1.1274x; 1.1274x over previous
#include <cuda_runtime.h>

// CrossNet closed form:
//   out = (a1*a2*a3)*x + (a2*a3)*b1 + a3*b2 + b3
//   d_k = x . w_k   (3 dots of the SAME x -> one reduction round)
//   a1 = d1+1; a2 = a1*d2 + c12 + 1; a3 = a2*(a1*d3 + c13) + c23 + 1
//   c12=b1.w2, c13=b1.w3, c23=b2.w3 (row-independent, tiny pre-kernel)
// B=16384, D=2048, fp32. R=4 rows per CTA, 512 threads.

#define D 2048
#define VEC (D / 4)          // 512 float4 per row
#define THREADS 512
#define NWARP (THREADS / 32) // 16
#define R 4

__device__ float g_c[4];     // c12, c13, c23

// ---------- tiny pre-kernel: weight/bias cross-dots ----------
__global__ void crossnet_const_kernel(const float4* __restrict__ w2,
                                      const float4* __restrict__ w3,
                                      const float4* __restrict__ b1,
                                      const float4* __restrict__ b2)
{
    __shared__ float sh[NWARP][3];
    const int t = threadIdx.x, lane = t & 31, wid = t >> 5;

    const float4 w2v = w2[t], w3v = w3[t], b1v = b1[t], b2v = b2[t];
    float q12 = b1v.x*w2v.x + b1v.y*w2v.y + b1v.z*w2v.z + b1v.w*w2v.w;
    float q13 = b1v.x*w3v.x + b1v.y*w3v.y + b1v.z*w3v.z + b1v.w*w3v.w;
    float q23 = b2v.x*w3v.x + b2v.y*w3v.y + b2v.z*w3v.z + b2v.w*w3v.w;

    #pragma unroll
    for (int off = 16; off > 0; off >>= 1) {
        q12 += __shfl_xor_sync(0xFFFFFFFFu, q12, off);
        q13 += __shfl_xor_sync(0xFFFFFFFFu, q13, off);
        q23 += __shfl_xor_sync(0xFFFFFFFFu, q23, off);
    }
    if (lane == 0) { sh[wid][0] = q12; sh[wid][1] = q13; sh[wid][2] = q23; }
    __syncthreads();
    if (t == 0) {
        float c12 = 0.f, c13 = 0.f, c23 = 0.f;
        #pragma unroll
        for (int j = 0; j < NWARP; ++j) {
            c12 += sh[j][0]; c13 += sh[j][1]; c23 += sh[j][2];
        }
        g_c[0] = c12; g_c[1] = c13; g_c[2] = c23;
    }
}

// ---------- main kernel ----------
__global__ __launch_bounds__(THREADS, 4)
void crossnet_kernel(const float4* __restrict__ x,
                     const float4* __restrict__ w1, const float4* __restrict__ b1,
                     const float4* __restrict__ w2, const float4* __restrict__ b2,
                     const float4* __restrict__ w3, const float4* __restrict__ b3,
                     float4* __restrict__ out)
{
    __shared__ float4 sh_p1[NWARP], sh_p2[NWARP], sh_p3[NWARP]; // per-warp partials (4 rows)
    __shared__ float4 sh_c[R];                                   // per-row (m, k1, k2, _)

    const int t    = threadIdx.x;
    const int lane = t & 31;
    const int wid  = t >> 5;
    const long long base = (long long)blockIdx.x * (R * VEC) + t;

    // 4 independent streaming row loads (MLP=4)
    float4 y[R];
    #pragma unroll
    for (int r = 0; r < R; ++r)
        y[r] = __ldcs(&x[base + (long long)r * VEC]);

    // --- three dots of x, reduced per-warp immediately (low reg pressure) ---
    {
        const float4 wv = __ldg(&w1[t]);
        float p[R];
        #pragma unroll
        for (int r = 0; r < R; ++r)
            p[r] = y[r].x*wv.x + y[r].y*wv.y + y[r].z*wv.z + y[r].w*wv.w;
        #pragma unroll
        for (int off = 16; off > 0; off >>= 1) {
            #pragma unroll
            for (int r = 0; r < R; ++r) p[r] += __shfl_xor_sync(0xFFFFFFFFu, p[r], off);
        }
        if (lane == 0) sh_p1[wid] = make_float4(p[0], p[1], p[2], p[3]);
    }
    {
        const float4 wv = __ldg(&w2[t]);
        float p[R];
        #pragma unroll
        for (int r = 0; r < R; ++r)
            p[r] = y[r].x*wv.x + y[r].y*wv.y + y[r].z*wv.z + y[r].w*wv.w;
        #pragma unroll
        for (int off = 16; off > 0; off >>= 1) {
            #pragma unroll
            for (int r = 0; r < R; ++r) p[r] += __shfl_xor_sync(0xFFFFFFFFu, p[r], off);
        }
        if (lane == 0) sh_p2[wid] = make_float4(p[0], p[1], p[2], p[3]);
    }
    {
        const float4 wv = __ldg(&w3[t]);
        float p[R];
        #pragma unroll
        for (int r = 0; r < R; ++r)
            p[r] = y[r].x*wv.x + y[r].y*wv.y + y[r].z*wv.z + y[r].w*wv.w;
        #pragma unroll
        for (int off = 16; off > 0; off >>= 1) {
            #pragma unroll
            for (int r = 0; r < R; ++r) p[r] += __shfl_xor_sync(0xFFFFFFFFu, p[r], off);
        }
        if (lane == 0) sh_p3[wid] = make_float4(p[0], p[1], p[2], p[3]);
    }
    __syncthreads();

    // --- warp0: cross-warp reduce (16 partials) + coefficient computation ---
    if (wid == 0) {
        const bool ok = lane < NWARP;
        float4 v1 = ok ? sh_p1[lane] : make_float4(0.f,0.f,0.f,0.f);
        float4 v2 = ok ? sh_p2[lane] : make_float4(0.f,0.f,0.f,0.f);
        float4 v3 = ok ? sh_p3[lane] : make_float4(0.f,0.f,0.f,0.f);
        #pragma unroll
        for (int off = 8; off > 0; off >>= 1) {
            v1.x += __shfl_xor_sync(0xFFFFFFFFu, v1.x, off);
            v1.y += __shfl_xor_sync(0xFFFFFFFFu, v1.y, off);
            v1.z += __shfl_xor_sync(0xFFFFFFFFu, v1.z, off);
            v1.w += __shfl_xor_sync(0xFFFFFFFFu, v1.w, off);
            v2.x += __shfl_xor_sync(0xFFFFFFFFu, v2.x, off);
            v2.y += __shfl_xor_sync(0xFFFFFFFFu, v2.y, off);
            v2.z += __shfl_xor_sync(0xFFFFFFFFu, v2.z, off);
            v2.w += __shfl_xor_sync(0xFFFFFFFFu, v2.w, off);
            v3.x += __shfl_xor_sync(0xFFFFFFFFu, v3.x, off);
            v3.y += __shfl_xor_sync(0xFFFFFFFFu, v3.y, off);
            v3.z += __shfl_xor_sync(0xFFFFFFFFu, v3.z, off);
            v3.w += __shfl_xor_sync(0xFFFFFFFFu, v3.w, off);
        }
        if (lane == 0) {
            const float c12 = g_c[0], c13 = g_c[1], c23 = g_c[2];
            const float d1[R] = {v1.x, v1.y, v1.z, v1.w};
            const float d2[R] = {v2.x, v2.y, v2.z, v2.w};
            const float d3[R] = {v3.x, v3.y, v3.z, v3.w};
            #pragma unroll
            for (int r = 0; r < R; ++r) {
                const float a1 = d1[r] + 1.0f;
                const float a2 = fmaf(a1, d2[r], c12) + 1.0f;
                const float a3 = fmaf(a2, fmaf(a1, d3[r], c13), c23) + 1.0f;
                const float k1 = a2 * a3;          // coeff of b1
                const float m  = a1 * k1;          // coeff of x
                sh_c[r] = make_float4(m, k1, a3, 0.0f);
            }
        }
    }
    __syncthreads();

    // --- fused epilogue: out = m*x + k1*b1 + k2*b2 + b3 ---
    const float4 bv1 = __ldg(&b1[t]);
    const float4 bv2 = __ldg(&b2[t]);
    const float4 bv3 = __ldg(&b3[t]);

    #pragma unroll
    for (int r = 0; r < R; ++r) {
        const float4 c = sh_c[r];   // m, k1, k2
        float4 o;
        o.x = fmaf(y[r].x, c.x, fmaf(bv1.x, c.y, fmaf(bv2.x, c.z, bv3.x)));
        o.y = fmaf(y[r].y, c.x, fmaf(bv1.y, c.y, fmaf(bv2.y, c.z, bv3.y)));
        o.z = fmaf(y[r].z, c.x, fmaf(bv1.z, c.y, fmaf(bv2.z, c.z, bv3.z)));
        o.w = fmaf(y[r].w, c.x, fmaf(bv1.w, c.y, fmaf(bv2.w, c.z, bv3.w)));
        __stcs(&out[base + (long long)r * VEC], o);
    }
}

extern "C" void kernel_launch(void* const* d_in, const int* in_sizes, int n_in,
                              void* d_out, int out_size)
{
    const float4* x  = (const float4*)d_in[0];
    const float4* w1 = (const float4*)d_in[1];
    const float4* b1 = (const float4*)d_in[2];
    const float4* w2 = (const float4*)d_in[3];
    const float4* b2 = (const float4*)d_in[4];
    const float4* w3 = (const float4*)d_in[5];
    const float4* b3 = (const float4*)d_in[6];
    float4* out = (float4*)d_out;

    const int B = in_sizes[0] / D;   // 16384

    crossnet_const_kernel<<<1, THREADS>>>(w2, w3, b1, b2);
    crossnet_kernel<<<B / R, THREADS>>>(x, w1, b1, w2, b2, w3, b3, out);
}